// round 8
// baseline (speedup 1.0000x reference)
#include <cuda_runtime.h>
#include <cuda_bf16.h>
#include <math.h>
#include <stdint.h>

#define Bsz 32768
#define Fn 16
#define Hn 64
#define On 32
#define En 16
#define BM 128
#define TILES 8
#define GRPS 32          // GRPS*TILES*BM = 32768
#define HP 36            // uint32 pitch (36 = 4 mod 32 -> conflict-free fragments)

// ---------------- device scratch ----------------
__device__ float g_tok[(size_t)Bsz * Fn * En];   // 33.5 MB: tok[B][F][E]
__device__ float g_Mt[En * En];                   // (Wq@Wk^T)^T / 4, [j'][j]
__device__ float g_wb[En];                        // Wk@bq / 4
__device__ float g_wvec[En];                      // Wv@Wo@Wf
__device__ float g_c0[1];                         // bv.(Wo@Wf) + bo.Wf + bf

// ---------------- helpers ----------------
__device__ __forceinline__ float leaky(float v) { return v >= 0.f ? v : 0.01f * v; }
__device__ __forceinline__ float2 splat2(float s) { return make_float2(s, s); }
__device__ __forceinline__ float2 ffma2(float2 a, float2 b, float2 c) {
  float2 d;
  asm("fma.rn.f32x2 %0, %1, %2, %3;"
      : "=l"(*(unsigned long long*)&d)
      : "l"(*(unsigned long long*)&a), "l"(*(unsigned long long*)&b),
        "l"(*(unsigned long long*)&c));
  return d;
}

__device__ __forceinline__ uint32_t bfpack(float lo, float hi) {
  uint32_t r;
  asm("cvt.rn.bf16x2.f32 %0, %1, %2;" : "=r"(r) : "f"(hi), "f"(lo));
  return r;
}
__device__ __forceinline__ void split_pair(float v0, float v1, uint32_t& hi, uint32_t& lo) {
  float h0 = __bfloat162float(__float2bfloat16(v0));
  float h1 = __bfloat162float(__float2bfloat16(v1));
  hi = bfpack(h0, h1);
  lo = bfpack(v0 - h0, v1 - h1);
}

__device__ __forceinline__ void mma_bf16(float* c, uint32_t a0, uint32_t a1, uint32_t a2,
                                         uint32_t a3, uint32_t b0, uint32_t b1) {
  asm volatile(
      "mma.sync.aligned.m16n8k16.row.col.f32.bf16.bf16.f32 "
      "{%0,%1,%2,%3}, {%4,%5,%6,%7}, {%8,%9}, {%0,%1,%2,%3};"
      : "+f"(c[0]), "+f"(c[1]), "+f"(c[2]), "+f"(c[3])
      : "r"(a0), "r"(a1), "r"(a2), "r"(a3), "r"(b0), "r"(b1));
}

// ---------------- pass 1 smem (h double-buffered) ----------------
struct __align__(16) SM {
  uint32_t h1Hi[BM * HP];    // 18432 B
  uint32_t h1Lo[BM * HP];
  uint32_t h2Hi[BM * HP];
  uint32_t h2Lo[BM * HP];
  uint32_t w3Hi[En * HP];    // 2304 B
  uint32_t w3Lo[En * HP];
  float W1s[Hn], b1s[Hn], b2s[Hn];
  float b3ps[En];
  float w3tmp[Hn * En];      // 4096 B
};

__global__ __launch_bounds__(128) void k_subnet(
    const float* __restrict__ x, const float* __restrict__ W1,
    const float* __restrict__ b1, const float* __restrict__ W2,
    const float* __restrict__ b2, const float* __restrict__ W3,
    const float* __restrict__ b3, const float* __restrict__ Wp,
    const float* __restrict__ bp, const float* __restrict__ Wqkv,
    const float* __restrict__ bqkv, const float* __restrict__ Wo,
    const float* __restrict__ bo, const float* __restrict__ Wf,
    const float* __restrict__ bf) {
  extern __shared__ char smraw[];
  SM& s = *reinterpret_cast<SM*>(smraw);
  const int tid = threadIdx.x;
  const int lane = tid & 31;
  const int wid = tid >> 5;
  const int f = blockIdx.x;
  const int grp = blockIdx.y;
  const int q = lane >> 2;
  const int l3 = lane & 3;

  // ---- fold (block (0,0) only): Mt, wb, wvec, c0 for k_attn ----
  if (blockIdx.x == 0 && blockIdx.y == 0) {
    if (tid < 16) {
      int d = tid;
      float acc = 0.f;
      for (int e = 0; e < En; e++) {
        float w = 0.f;
        for (int e2 = 0; e2 < En; e2++) w += Wo[e * En + e2] * Wf[e2];
        acc += Wqkv[d * 48 + 32 + e] * w;
      }
      g_wvec[d] = acc;
    } else if (tid < 32) {
      int j2 = tid - 16;
      float acc = 0.f;
      for (int d = 0; d < En; d++) acc += Wqkv[j2 * 48 + 16 + d] * bqkv[d];
      g_wb[j2] = 0.25f * acc;
    } else if (tid == 32) {
      float acc = bf[0];
      for (int e = 0; e < En; e++) {
        float w = 0.f;
        for (int e2 = 0; e2 < En; e2++) w += Wo[e * En + e2] * Wf[e2];
        acc += bqkv[32 + e] * w;
        acc += bo[e] * Wf[e];
      }
      g_c0[0] = acc;
    }
    for (int i = tid; i < 256; i += 128) {
      int j2 = i >> 4, j = i & 15;   // Mt[j'][j] = Wq[j].Wk[j'] / 4
      float acc = 0.f;
      for (int d = 0; d < En; d++) acc += Wqkv[j * 48 + d] * Wqkv[j2 * 48 + 16 + d];
      g_Mt[i] = 0.25f * acc;
    }
  }

  // ---- per-CTA init ----
  if (tid < Hn) {
    s.W1s[tid] = W1[f * Hn + tid];
    s.b1s[tid] = b1[f * Hn + tid];
    s.b2s[tid] = b2[f * Hn + tid];
  }
  if (tid < En) {
    float acc = bp[tid];
    for (int o = 0; o < On; o++) acc += b3[f * On + o] * Wp[o * En + tid];
    s.b3ps[tid] = acc;
  }
  for (int i = tid; i < Hn * En; i += 128) {
    int h = i >> 4, e = i & 15;
    float acc = 0.f;
#pragma unroll 8
    for (int o = 0; o < On; o++) acc += W3[f * Hn * On + h * On + o] * Wp[o * En + e];
    s.w3tmp[i] = acc;
  }

  uint32_t B2h[8][2], B2l[8][2];
  {
    const float* W2g = W2 + (size_t)f * Hn * Hn;
    const int n = wid * 16 + q;
#pragma unroll
    for (int nt = 0; nt < 2; nt++)
#pragma unroll
      for (int sstep = 0; sstep < 4; sstep++) {
        int nn = n + nt * 8;
        int k0 = sstep * 16 + 2 * l3;
        split_pair(W2g[k0 * Hn + nn], W2g[(k0 + 1) * Hn + nn],
                   B2h[nt * 4 + sstep][0], B2l[nt * 4 + sstep][0]);
        split_pair(W2g[(k0 + 8) * Hn + nn], W2g[(k0 + 9) * Hn + nn],
                   B2h[nt * 4 + sstep][1], B2l[nt * 4 + sstep][1]);
      }
  }
  __syncthreads();

  for (int i = tid; i < En * 32; i += 128) {
    int n = i >> 5, kp = i & 31;
    split_pair(s.w3tmp[(2 * kp) * En + n], s.w3tmp[(2 * kp + 1) * En + n],
               s.w3Hi[n * HP + kp], s.w3Lo[n * HP + kp]);
  }
  __syncthreads();

  const int tile0 = grp * TILES;
  float xv = x[(size_t)(tile0 * BM + tid) * Fn + f];

  for (int t = 0; t < TILES; t++) {
    const int b0row = (tile0 + t) * BM;

    // ---- layer 1 -> h1 ----
#pragma unroll
    for (int kb = 0; kb < 16; kb++) {
      float4 w = ((const float4*)s.W1s)[kb];
      float4 bb = ((const float4*)s.b1s)[kb];
      float v0 = leaky(fmaf(xv, w.x, bb.x));
      float v1 = leaky(fmaf(xv, w.y, bb.y));
      float v2 = leaky(fmaf(xv, w.z, bb.z));
      float v3 = leaky(fmaf(xv, w.w, bb.w));
      split_pair(v0, v1, s.h1Hi[tid * HP + kb * 2], s.h1Lo[tid * HP + kb * 2]);
      split_pair(v2, v3, s.h1Hi[tid * HP + kb * 2 + 1], s.h1Lo[tid * HP + kb * 2 + 1]);
    }
    if (t + 1 < TILES)
      xv = x[(size_t)(b0row + BM + tid) * Fn + f];
    __syncthreads();   // A: h1 ready

    // ---- layer 2: read h1 ----
    float C[8][2][4];
#pragma unroll
    for (int mt = 0; mt < 8; mt++)
#pragma unroll
      for (int nt = 0; nt < 2; nt++)
#pragma unroll
        for (int i = 0; i < 4; i++) C[mt][nt][i] = 0.f;

#pragma unroll
    for (int mt = 0; mt < 8; mt++) {
      const int r0 = mt * 16 + q;
#pragma unroll
      for (int sstep = 0; sstep < 4; sstep++) {
        const int ai = sstep * 8 + l3;
        uint32_t a0h = s.h1Hi[r0 * HP + ai],       a1h = s.h1Hi[(r0 + 8) * HP + ai];
        uint32_t a2h = s.h1Hi[r0 * HP + ai + 4],   a3h = s.h1Hi[(r0 + 8) * HP + ai + 4];
        uint32_t a0l = s.h1Lo[r0 * HP + ai],       a1l = s.h1Lo[(r0 + 8) * HP + ai];
        uint32_t a2l = s.h1Lo[r0 * HP + ai + 4],   a3l = s.h1Lo[(r0 + 8) * HP + ai + 4];
#pragma unroll
        for (int nt = 0; nt < 2; nt++) {
          mma_bf16(C[mt][nt], a0h, a1h, a2h, a3h, B2h[nt * 4 + sstep][0], B2h[nt * 4 + sstep][1]);
          mma_bf16(C[mt][nt], a0h, a1h, a2h, a3h, B2l[nt * 4 + sstep][0], B2l[nt * 4 + sstep][1]);
          mma_bf16(C[mt][nt], a0l, a1l, a2l, a3l, B2h[nt * 4 + sstep][0], B2h[nt * 4 + sstep][1]);
        }
      }
    }

    // ---- epilogue 2 -> h2 (separate buffer, no sync needed before) ----
#pragma unroll
    for (int mt = 0; mt < 8; mt++) {
      const int r0 = mt * 16 + q;
#pragma unroll
      for (int nt = 0; nt < 2; nt++) {
        const int n0 = wid * 16 + nt * 8 + 2 * l3;
        const int ci = wid * 8 + nt * 4 + l3;
        float v0 = leaky(C[mt][nt][0] + s.b2s[n0]);
        float v1 = leaky(C[mt][nt][1] + s.b2s[n0 + 1]);
        split_pair(v0, v1, s.h2Hi[r0 * HP + ci], s.h2Lo[r0 * HP + ci]);
        float v2 = leaky(C[mt][nt][2] + s.b2s[n0]);
        float v3 = leaky(C[mt][nt][3] + s.b2s[n0 + 1]);
        split_pair(v2, v3, s.h2Hi[(r0 + 8) * HP + ci], s.h2Lo[(r0 + 8) * HP + ci]);
      }
    }
    __syncthreads();   // B: h2 ready (and implies everyone's h1 reads done)

    // ---- layer 3: read h2 ----
    float C3[2][2][4];
#pragma unroll
    for (int mt2 = 0; mt2 < 2; mt2++)
#pragma unroll
      for (int nt = 0; nt < 2; nt++)
#pragma unroll
        for (int i = 0; i < 4; i++) C3[mt2][nt][i] = 0.f;

#pragma unroll
    for (int mt2 = 0; mt2 < 2; mt2++) {
      const int r0 = wid * 32 + mt2 * 16 + q;
#pragma unroll
      for (int sstep = 0; sstep < 4; sstep++) {
        const int ai = sstep * 8 + l3;
        uint32_t a0h = s.h2Hi[r0 * HP + ai],       a1h = s.h2Hi[(r0 + 8) * HP + ai];
        uint32_t a2h = s.h2Hi[r0 * HP + ai + 4],   a3h = s.h2Hi[(r0 + 8) * HP + ai + 4];
        uint32_t a0l = s.h2Lo[r0 * HP + ai],       a1l = s.h2Lo[(r0 + 8) * HP + ai];
        uint32_t a2l = s.h2Lo[r0 * HP + ai + 4],   a3l = s.h2Lo[(r0 + 8) * HP + ai + 4];
        const int kb = l3 + sstep * 8;
#pragma unroll
        for (int nt = 0; nt < 2; nt++) {
          const int nn = nt * 8 + q;
          uint32_t b0h = s.w3Hi[nn * HP + kb], b1h = s.w3Hi[nn * HP + kb + 4];
          uint32_t b0l = s.w3Lo[nn * HP + kb], b1l = s.w3Lo[nn * HP + kb + 4];
          mma_bf16(C3[mt2][nt], a0h, a1h, a2h, a3h, b0h, b1h);
          mma_bf16(C3[mt2][nt], a0h, a1h, a2h, a3h, b0l, b1l);
          mma_bf16(C3[mt2][nt], a0l, a1l, a2l, a3l, b0h, b1h);
        }
      }
    }

#pragma unroll
    for (int mt2 = 0; mt2 < 2; mt2++) {
      const int r0 = wid * 32 + mt2 * 16 + q;
#pragma unroll
      for (int nt = 0; nt < 2; nt++) {
        const int n0 = nt * 8 + 2 * l3;
        float2 d0 = make_float2(C3[mt2][nt][0] + s.b3ps[n0], C3[mt2][nt][1] + s.b3ps[n0 + 1]);
        float2 d1 = make_float2(C3[mt2][nt][2] + s.b3ps[n0], C3[mt2][nt][3] + s.b3ps[n0 + 1]);
        *(float2*)&g_tok[(size_t)(b0row + r0) * (Fn * En) + f * En + n0] = d0;
        *(float2*)&g_tok[(size_t)(b0row + r0 + 8) * (Fn * En) + f * En + n0] = d1;
      }
    }
    // no sync: next layer-1 writes h1, whose last reads precede barrier B
  }
}

// ---------------- pass 2: attention (q-proj eliminated via M = WqWk^T/4) ----------------
#define KSP 5   // float4 pitch per token
#define KSG 84  // float4 stride per group

__global__ __launch_bounds__(256) void k_attn(float* __restrict__ out) {
  __shared__ float4 ms4[16 * KSG];     // m_t tiles (21504 B)
  __shared__ float2 bz_s[16][17];      // (beta, z) per token
  __shared__ float Ms[En][En];         // Mt[j'][j]
  __shared__ float wbs[En], wvs[En];
  __shared__ float c0s;

  const int tid = threadIdx.x;
  Ms[tid >> 4][tid & 15] = g_Mt[tid];          // 256 threads exactly
  if (tid < En) { wbs[tid] = g_wb[tid]; wvs[tid] = g_wvec[tid]; }
  if (tid == 16) c0s = g_c0[0];
  __syncthreads();

  const int g = tid >> 4;
  const int t = tid & 15;
  const size_t b = (size_t)blockIdx.x * 16 + g;

  // my token (also the query vector)
  float tk[16];
  {
    const float4* tp = (const float4*)(g_tok + b * (Fn * En) + (size_t)t * En);
#pragma unroll
    for (int i = 0; i < 4; i++) {
      float4 v = tp[i];
      tk[i * 4 + 0] = v.x; tk[i * 4 + 1] = v.y;
      tk[i * 4 + 2] = v.z; tk[i * 4 + 3] = v.w;
    }
  }

  // m_t = Mt-rows weighted by tk ; beta_t = tk.wb ; z_t = tk.wvec
  float2 m2[8];
#pragma unroll
  for (int e = 0; e < 8; e++) m2[e] = make_float2(0.f, 0.f);
  float beta = 0.f, z = 0.f;
#pragma unroll
  for (int j = 0; j < 16; j++) {
    float2 aa = splat2(tk[j]);
    const float2* wrow = (const float2*)&Ms[j][0];
#pragma unroll
    for (int e = 0; e < 8; e++) m2[e] = ffma2(aa, wrow[e], m2[e]);
    beta = fmaf(tk[j], wbs[j], beta);
    z = fmaf(tk[j], wvs[j], z);
  }

  // publish
#pragma unroll
  for (int i = 0; i < 4; i++)
    ms4[g * KSG + t * KSP + i] =
        make_float4(m2[2 * i].x, m2[2 * i].y, m2[2 * i + 1].x, m2[2 * i + 1].y);
  bz_s[g][t] = make_float2(beta, z);
  __syncwarp(0xffffffffu);

  // scores: s[j] = tk . m_j + beta_j
  float sc[16];
#pragma unroll
  for (int j = 0; j < 16; j++) {
    const float4* kr = &ms4[g * KSG + j * KSP];
    float2 acc = make_float2(0.f, 0.f);
#pragma unroll
    for (int i = 0; i < 4; i++) {
      float4 kv = kr[i];
      acc = ffma2(make_float2(tk[4 * i], tk[4 * i + 1]), make_float2(kv.x, kv.y), acc);
      acc = ffma2(make_float2(tk[4 * i + 2], tk[4 * i + 3]), make_float2(kv.z, kv.w), acc);
    }
    sc[j] = acc.x + acc.y + bz_s[g][j].x;
  }

  // softmax + weighted z
  float mx = sc[0];
#pragma unroll
  for (int j = 1; j < 16; j++) mx = fmaxf(mx, sc[j]);
  float sum = 0.f, zacc = 0.f;
#pragma unroll
  for (int j = 0; j < 16; j++) {
    float e = __expf(sc[j] - mx);
    sum += e;
    zacc = fmaf(e, bz_s[g][j].y, zacc);
  }
  float rowval = zacc / sum;

#pragma unroll
  for (int off = 8; off; off >>= 1)
    rowval += __shfl_xor_sync(0xffffffffu, rowval, off);

  if (t == 0) out[b] = leaky(rowval * (1.f / 16.f) + c0s);
}

// ---------------- launch ----------------
extern "C" void kernel_launch(void* const* d_in, const int* in_sizes, int n_in,
                              void* d_out, int out_size) {
  const float* x    = (const float*)d_in[0];
  const float* W1   = (const float*)d_in[1];
  const float* b1   = (const float*)d_in[2];
  const float* W2   = (const float*)d_in[3];
  const float* b2   = (const float*)d_in[4];
  const float* W3   = (const float*)d_in[5];
  const float* b3   = (const float*)d_in[6];
  const float* Wp   = (const float*)d_in[7];
  const float* bp   = (const float*)d_in[8];
  const float* Wqkv = (const float*)d_in[9];
  const float* bqkv = (const float*)d_in[10];
  const float* Wo   = (const float*)d_in[11];
  const float* bo   = (const float*)d_in[12];
  const float* Wf   = (const float*)d_in[13];
  const float* bf   = (const float*)d_in[14];
  float* out = (float*)d_out;

  (void)in_sizes; (void)n_in; (void)out_size;

  cudaFuncSetAttribute(k_subnet, cudaFuncAttributeMaxDynamicSharedMemorySize,
                       (int)sizeof(SM));

  dim3 g1(Fn, GRPS);
  k_subnet<<<g1, 128, sizeof(SM)>>>(x, W1, b1, W2, b2, W3, b3, Wp, bp,
                                    Wqkv, bqkv, Wo, bo, Wf, bf);
  k_attn<<<Bsz / 16, 256>>>(out);
}

// round 9
// speedup vs baseline: 1.1197x; 1.1197x over previous
#include <cuda_runtime.h>
#include <cuda_bf16.h>
#include <math.h>
#include <stdint.h>

#define Bsz 32768
#define Fn 16
#define Hn 64
#define On 32
#define En 16
#define BM 128
#define TILES 8
#define GRPS 32          // GRPS*TILES*BM = 32768
#define HP 36            // uint32 pitch (36 = 4 mod 32 -> conflict-free fragments)

// ---------------- device scratch ----------------
__device__ float g_tok[(size_t)Bsz * Fn * En];   // 33.5 MB: tok[B][F][E]
__device__ float g_Mt[En * En];                   // (Wq@Wk^T)^T / 4, [j'][j]
__device__ float g_wb[En];                        // Wk@bq / 4
__device__ float g_wvec[En];                      // Wv@Wo@Wf
__device__ float g_c0[1];                         // bv.(Wo@Wf) + bo.Wf + bf

// ---------------- helpers ----------------
__device__ __forceinline__ float leaky(float v) { return v >= 0.f ? v : 0.01f * v; }
__device__ __forceinline__ float2 splat2(float s) { return make_float2(s, s); }
__device__ __forceinline__ float2 ffma2(float2 a, float2 b, float2 c) {
  float2 d;
  asm("fma.rn.f32x2 %0, %1, %2, %3;"
      : "=l"(*(unsigned long long*)&d)
      : "l"(*(unsigned long long*)&a), "l"(*(unsigned long long*)&b),
        "l"(*(unsigned long long*)&c));
  return d;
}

__device__ __forceinline__ uint32_t bfpack(float lo, float hi) {
  uint32_t r;
  asm("cvt.rn.bf16x2.f32 %0, %1, %2;" : "=r"(r) : "f"(hi), "f"(lo));
  return r;
}
__device__ __forceinline__ void split_pair(float v0, float v1, uint32_t& hi, uint32_t& lo) {
  float h0 = __bfloat162float(__float2bfloat16(v0));
  float h1 = __bfloat162float(__float2bfloat16(v1));
  hi = bfpack(h0, h1);
  lo = bfpack(v0 - h0, v1 - h1);
}

__device__ __forceinline__ void mma_bf16(float* c, uint32_t a0, uint32_t a1, uint32_t a2,
                                         uint32_t a3, uint32_t b0, uint32_t b1) {
  asm volatile(
      "mma.sync.aligned.m16n8k16.row.col.f32.bf16.bf16.f32 "
      "{%0,%1,%2,%3}, {%4,%5,%6,%7}, {%8,%9}, {%0,%1,%2,%3};"
      : "+f"(c[0]), "+f"(c[1]), "+f"(c[2]), "+f"(c[3])
      : "r"(a0), "r"(a1), "r"(a2), "r"(a3), "r"(b0), "r"(b1));
}

// ---------------- pass 1 smem (single h buffer -> ~45 KB, 4-5 CTAs/SM) ----------------
struct __align__(16) SM {
  uint32_t hHi[BM * HP];     // 18432 B  packed bf16x2 (hi)
  uint32_t hLo[BM * HP];     // 18432 B  (lo)
  uint32_t w3Hi[En * HP];    // 2304 B   W3p pairs [n][kp]
  uint32_t w3Lo[En * HP];    // 2304 B
  float W1s[Hn], b1s[Hn], b2s[Hn];
  float b3ps[En];
  float w3tmp[Hn * En];      // 4096 B
};

__global__ __launch_bounds__(128) void k_subnet(
    const float* __restrict__ x, const float* __restrict__ W1,
    const float* __restrict__ b1, const float* __restrict__ W2,
    const float* __restrict__ b2, const float* __restrict__ W3,
    const float* __restrict__ b3, const float* __restrict__ Wp,
    const float* __restrict__ bp, const float* __restrict__ Wqkv,
    const float* __restrict__ bqkv, const float* __restrict__ Wo,
    const float* __restrict__ bo, const float* __restrict__ Wf,
    const float* __restrict__ bf) {
  extern __shared__ char smraw[];
  SM& s = *reinterpret_cast<SM*>(smraw);
  const int tid = threadIdx.x;
  const int lane = tid & 31;
  const int wid = tid >> 5;
  const int f = blockIdx.x;
  const int grp = blockIdx.y;
  const int q = lane >> 2;
  const int l3 = lane & 3;

  // ---- fold (block (0,0) only): Mt, wb, wvec, c0 for k_attn ----
  if (blockIdx.x == 0 && blockIdx.y == 0) {
    if (tid < 16) {
      int d = tid;
      float acc = 0.f;
      for (int e = 0; e < En; e++) {
        float w = 0.f;
        for (int e2 = 0; e2 < En; e2++) w += Wo[e * En + e2] * Wf[e2];
        acc += Wqkv[d * 48 + 32 + e] * w;
      }
      g_wvec[d] = acc;
    } else if (tid < 32) {
      int j2 = tid - 16;
      float acc = 0.f;
      for (int d = 0; d < En; d++) acc += Wqkv[j2 * 48 + 16 + d] * bqkv[d];
      g_wb[j2] = 0.25f * acc;
    } else if (tid == 32) {
      float acc = bf[0];
      for (int e = 0; e < En; e++) {
        float w = 0.f;
        for (int e2 = 0; e2 < En; e2++) w += Wo[e * En + e2] * Wf[e2];
        acc += bqkv[32 + e] * w;
        acc += bo[e] * Wf[e];
      }
      g_c0[0] = acc;
    }
    for (int i = tid; i < 256; i += 128) {
      int j2 = i >> 4, j = i & 15;   // Mt[j'][j] = Wq[j].Wk[j'] / 4
      float acc = 0.f;
      for (int d = 0; d < En; d++) acc += Wqkv[j * 48 + d] * Wqkv[j2 * 48 + 16 + d];
      g_Mt[i] = 0.25f * acc;
    }
  }

  // ---- per-CTA init ----
  if (tid < Hn) {
    s.W1s[tid] = W1[f * Hn + tid];
    s.b1s[tid] = b1[f * Hn + tid];
    s.b2s[tid] = b2[f * Hn + tid];
  }
  if (tid < En) {
    float acc = bp[tid];
    for (int o = 0; o < On; o++) acc += b3[f * On + o] * Wp[o * En + tid];
    s.b3ps[tid] = acc;
  }
  for (int i = tid; i < Hn * En; i += 128) {
    int h = i >> 4, e = i & 15;
    float acc = 0.f;
#pragma unroll 8
    for (int o = 0; o < On; o++) acc += W3[f * Hn * On + h * On + o] * Wp[o * En + e];
    s.w3tmp[i] = acc;
  }

  uint32_t B2h[8][2], B2l[8][2];
  {
    const float* W2g = W2 + (size_t)f * Hn * Hn;
    const int n = wid * 16 + q;
#pragma unroll
    for (int nt = 0; nt < 2; nt++)
#pragma unroll
      for (int sstep = 0; sstep < 4; sstep++) {
        int nn = n + nt * 8;
        int k0 = sstep * 16 + 2 * l3;
        split_pair(W2g[k0 * Hn + nn], W2g[(k0 + 1) * Hn + nn],
                   B2h[nt * 4 + sstep][0], B2l[nt * 4 + sstep][0]);
        split_pair(W2g[(k0 + 8) * Hn + nn], W2g[(k0 + 9) * Hn + nn],
                   B2h[nt * 4 + sstep][1], B2l[nt * 4 + sstep][1]);
      }
  }
  __syncthreads();

  for (int i = tid; i < En * 32; i += 128) {
    int n = i >> 5, kp = i & 31;
    split_pair(s.w3tmp[(2 * kp) * En + n], s.w3tmp[(2 * kp + 1) * En + n],
               s.w3Hi[n * HP + kp], s.w3Lo[n * HP + kp]);
  }
  __syncthreads();

  const int tile0 = grp * TILES;
  float xv = x[(size_t)(tile0 * BM + tid) * Fn + f];

  for (int t = 0; t < TILES; t++) {
    const int b0row = (tile0 + t) * BM;

    // ---- layer 1 -> h ----
#pragma unroll
    for (int kb = 0; kb < 16; kb++) {
      float4 w = ((const float4*)s.W1s)[kb];
      float4 bb = ((const float4*)s.b1s)[kb];
      float v0 = leaky(fmaf(xv, w.x, bb.x));
      float v1 = leaky(fmaf(xv, w.y, bb.y));
      float v2 = leaky(fmaf(xv, w.z, bb.z));
      float v3 = leaky(fmaf(xv, w.w, bb.w));
      split_pair(v0, v1, s.hHi[tid * HP + kb * 2], s.hLo[tid * HP + kb * 2]);
      split_pair(v2, v3, s.hHi[tid * HP + kb * 2 + 1], s.hLo[tid * HP + kb * 2 + 1]);
    }
    if (t + 1 < TILES)
      xv = x[(size_t)(b0row + BM + tid) * Fn + f];
    __syncthreads();

    // ---- layer 2: C[128,64] = h1 @ W2, warp owns N=16 ----
    float C[8][2][4];
#pragma unroll
    for (int mt = 0; mt < 8; mt++)
#pragma unroll
      for (int nt = 0; nt < 2; nt++)
#pragma unroll
        for (int i = 0; i < 4; i++) C[mt][nt][i] = 0.f;

#pragma unroll
    for (int mt = 0; mt < 8; mt++) {
      const int r0 = mt * 16 + q;
#pragma unroll
      for (int sstep = 0; sstep < 4; sstep++) {
        const int ai = sstep * 8 + l3;
        uint32_t a0h = s.hHi[r0 * HP + ai],       a1h = s.hHi[(r0 + 8) * HP + ai];
        uint32_t a2h = s.hHi[r0 * HP + ai + 4],   a3h = s.hHi[(r0 + 8) * HP + ai + 4];
        uint32_t a0l = s.hLo[r0 * HP + ai],       a1l = s.hLo[(r0 + 8) * HP + ai];
        uint32_t a2l = s.hLo[r0 * HP + ai + 4],   a3l = s.hLo[(r0 + 8) * HP + ai + 4];
#pragma unroll
        for (int nt = 0; nt < 2; nt++) {
          mma_bf16(C[mt][nt], a0h, a1h, a2h, a3h, B2h[nt * 4 + sstep][0], B2h[nt * 4 + sstep][1]);
          mma_bf16(C[mt][nt], a0h, a1h, a2h, a3h, B2l[nt * 4 + sstep][0], B2l[nt * 4 + sstep][1]);
          mma_bf16(C[mt][nt], a0l, a1l, a2l, a3l, B2h[nt * 4 + sstep][0], B2h[nt * 4 + sstep][1]);
        }
      }
    }
    __syncthreads();   // all h1 reads done before overwriting with h2

    // ---- epilogue 2: h2 = leaky(C + b2) -> h (same buffer) ----
#pragma unroll
    for (int mt = 0; mt < 8; mt++) {
      const int r0 = mt * 16 + q;
#pragma unroll
      for (int nt = 0; nt < 2; nt++) {
        const int n0 = wid * 16 + nt * 8 + 2 * l3;
        const int ci = wid * 8 + nt * 4 + l3;
        float v0 = leaky(C[mt][nt][0] + s.b2s[n0]);
        float v1 = leaky(C[mt][nt][1] + s.b2s[n0 + 1]);
        split_pair(v0, v1, s.hHi[r0 * HP + ci], s.hLo[r0 * HP + ci]);
        float v2 = leaky(C[mt][nt][2] + s.b2s[n0]);
        float v3 = leaky(C[mt][nt][3] + s.b2s[n0 + 1]);
        split_pair(v2, v3, s.hHi[(r0 + 8) * HP + ci], s.hLo[(r0 + 8) * HP + ci]);
      }
    }
    __syncthreads();

    // ---- layer 3: D[128,16] = h2 @ W3p, warp owns M=32 ----
    float C3[2][2][4];
#pragma unroll
    for (int mt2 = 0; mt2 < 2; mt2++)
#pragma unroll
      for (int nt = 0; nt < 2; nt++)
#pragma unroll
        for (int i = 0; i < 4; i++) C3[mt2][nt][i] = 0.f;

#pragma unroll
    for (int mt2 = 0; mt2 < 2; mt2++) {
      const int r0 = wid * 32 + mt2 * 16 + q;
#pragma unroll
      for (int sstep = 0; sstep < 4; sstep++) {
        const int ai = sstep * 8 + l3;
        uint32_t a0h = s.hHi[r0 * HP + ai],       a1h = s.hHi[(r0 + 8) * HP + ai];
        uint32_t a2h = s.hHi[r0 * HP + ai + 4],   a3h = s.hHi[(r0 + 8) * HP + ai + 4];
        uint32_t a0l = s.hLo[r0 * HP + ai],       a1l = s.hLo[(r0 + 8) * HP + ai];
        uint32_t a2l = s.hLo[r0 * HP + ai + 4],   a3l = s.hLo[(r0 + 8) * HP + ai + 4];
        const int kb = l3 + sstep * 8;
#pragma unroll
        for (int nt = 0; nt < 2; nt++) {
          const int nn = nt * 8 + q;
          uint32_t b0h = s.w3Hi[nn * HP + kb], b1h = s.w3Hi[nn * HP + kb + 4];
          uint32_t b0l = s.w3Lo[nn * HP + kb], b1l = s.w3Lo[nn * HP + kb + 4];
          mma_bf16(C3[mt2][nt], a0h, a1h, a2h, a3h, b0h, b1h);
          mma_bf16(C3[mt2][nt], a0h, a1h, a2h, a3h, b0l, b1l);
          mma_bf16(C3[mt2][nt], a0l, a1l, a2l, a3l, b0h, b1h);
        }
      }
    }

    // ---- epilogue 3: + b3p, store tok ----
#pragma unroll
    for (int mt2 = 0; mt2 < 2; mt2++) {
      const int r0 = wid * 32 + mt2 * 16 + q;
#pragma unroll
      for (int nt = 0; nt < 2; nt++) {
        const int n0 = nt * 8 + 2 * l3;
        float2 d0 = make_float2(C3[mt2][nt][0] + s.b3ps[n0], C3[mt2][nt][1] + s.b3ps[n0 + 1]);
        float2 d1 = make_float2(C3[mt2][nt][2] + s.b3ps[n0], C3[mt2][nt][3] + s.b3ps[n0 + 1]);
        *(float2*)&g_tok[(size_t)(b0row + r0) * (Fn * En) + f * En + n0] = d0;
        *(float2*)&g_tok[(size_t)(b0row + r0 + 8) * (Fn * En) + f * En + n0] = d1;
      }
    }
    __syncthreads();   // h reused as h1 next tile
  }
}

// ---------------- pass 2: attention (q-proj eliminated via M = WqWk^T/4) ----------------
#define KSP 5   // float4 pitch per token
#define KSG 84  // float4 stride per group

__global__ __launch_bounds__(256) void k_attn(float* __restrict__ out) {
  __shared__ float4 ms4[16 * KSG];     // m_t tiles
  __shared__ float2 bz_s[16][17];      // (beta, z) per token
  __shared__ float Ms[En][En];         // Mt[j'][j]
  __shared__ float wbs[En], wvs[En];
  __shared__ float c0s;

  const int tid = threadIdx.x;
  Ms[tid >> 4][tid & 15] = g_Mt[tid];
  if (tid < En) { wbs[tid] = g_wb[tid]; wvs[tid] = g_wvec[tid]; }
  if (tid == 16) c0s = g_c0[0];
  __syncthreads();

  const int g = tid >> 4;
  const int t = tid & 15;
  const size_t b = (size_t)blockIdx.x * 16 + g;

  float tk[16];
  {
    const float4* tp = (const float4*)(g_tok + b * (Fn * En) + (size_t)t * En);
#pragma unroll
    for (int i = 0; i < 4; i++) {
      float4 v = tp[i];
      tk[i * 4 + 0] = v.x; tk[i * 4 + 1] = v.y;
      tk[i * 4 + 2] = v.z; tk[i * 4 + 3] = v.w;
    }
  }

  // m_t = Mt-rows weighted by tk ; beta_t = tk.wb ; z_t = tk.wvec
  float2 m2[8];
#pragma unroll
  for (int e = 0; e < 8; e++) m2[e] = make_float2(0.f, 0.f);
  float beta = 0.f, z = 0.f;
#pragma unroll
  for (int j = 0; j < 16; j++) {
    float2 aa = splat2(tk[j]);
    const float2* wrow = (const float2*)&Ms[j][0];
#pragma unroll
    for (int e = 0; e < 8; e++) m2[e] = ffma2(aa, wrow[e], m2[e]);
    beta = fmaf(tk[j], wbs[j], beta);
    z = fmaf(tk[j], wvs[j], z);
  }

#pragma unroll
  for (int i = 0; i < 4; i++)
    ms4[g * KSG + t * KSP + i] =
        make_float4(m2[2 * i].x, m2[2 * i].y, m2[2 * i + 1].x, m2[2 * i + 1].y);
  bz_s[g][t] = make_float2(beta, z);
  __syncwarp(0xffffffffu);

  // scores: s[j] = tk . m_j + beta_j
  float sc[16];
#pragma unroll
  for (int j = 0; j < 16; j++) {
    const float4* kr = &ms4[g * KSG + j * KSP];
    float2 acc = make_float2(0.f, 0.f);
#pragma unroll
    for (int i = 0; i < 4; i++) {
      float4 kv = kr[i];
      acc = ffma2(make_float2(tk[4 * i], tk[4 * i + 1]), make_float2(kv.x, kv.y), acc);
      acc = ffma2(make_float2(tk[4 * i + 2], tk[4 * i + 3]), make_float2(kv.z, kv.w), acc);
    }
    sc[j] = acc.x + acc.y + bz_s[g][j].x;
  }

  // softmax + weighted z
  float mx = sc[0];
#pragma unroll
  for (int j = 1; j < 16; j++) mx = fmaxf(mx, sc[j]);
  float sum = 0.f, zacc = 0.f;
#pragma unroll
  for (int j = 0; j < 16; j++) {
    float e = __expf(sc[j] - mx);
    sum += e;
    zacc = fmaf(e, bz_s[g][j].y, zacc);
  }
  float rowval = zacc / sum;

#pragma unroll
  for (int off = 8; off; off >>= 1)
    rowval += __shfl_xor_sync(0xffffffffu, rowval, off);

  if (t == 0) out[b] = leaky(rowval * (1.f / 16.f) + c0s);
}

// ---------------- launch ----------------
extern "C" void kernel_launch(void* const* d_in, const int* in_sizes, int n_in,
                              void* d_out, int out_size) {
  const float* x    = (const float*)d_in[0];
  const float* W1   = (const float*)d_in[1];
  const float* b1   = (const float*)d_in[2];
  const float* W2   = (const float*)d_in[3];
  const float* b2   = (const float*)d_in[4];
  const float* W3   = (const float*)d_in[5];
  const float* b3   = (const float*)d_in[6];
  const float* Wp   = (const float*)d_in[7];
  const float* bp   = (const float*)d_in[8];
  const float* Wqkv = (const float*)d_in[9];
  const float* bqkv = (const float*)d_in[10];
  const float* Wo   = (const float*)d_in[11];
  const float* bo   = (const float*)d_in[12];
  const float* Wf   = (const float*)d_in[13];
  const float* bf   = (const float*)d_in[14];
  float* out = (float*)d_out;

  (void)in_sizes; (void)n_in; (void)out_size;

  cudaFuncSetAttribute(k_subnet, cudaFuncAttributeMaxDynamicSharedMemorySize,
                       (int)sizeof(SM));

  dim3 g1(Fn, GRPS);
  k_subnet<<<g1, 128, sizeof(SM)>>>(x, W1, b1, W2, b2, W3, b3, Wp, bp,
                                    Wqkv, bqkv, Wo, bo, Wf, bf);
  k_attn<<<Bsz / 16, 256>>>(out);
}